// round 1
// baseline (speedup 1.0000x reference)
#include <cuda_runtime.h>

// Fixed problem shape (from reference): B=16, C=1, H=128, W=8192, NMAX=64
#define BB   16
#define HH   128
#define WW   8192
#define NMX  64

// Scratch (allocation-free rule: device globals)
__device__ int g_start[BB][NMX];
__device__ int g_end[BB][NMX];
__device__ int g_src0[BB][NMX];
__device__ int g_n[BB];

// ---------------------------------------------------------------------------
// Kernel 1: per-batch metadata. 16 blocks x 64 threads.
// Computes compressed segment starts/ends via a tiny Hillis-Steele scan,
// stashes them in device scratch, and writes xi_new to the output tail.
// ---------------------------------------------------------------------------
__global__ void meta_kernel(const int* __restrict__ xi,
                            const int* __restrict__ N,
                            float* __restrict__ out_xi,
                            int write_xi) {
    const int b = blockIdx.x;
    const int i = threadIdx.x;            // 0..63
    __shared__ int sh[NMX];

    const int n = N[b];
    const int s = xi[(b * NMX + i) * 2 + 0];
    const int e = xi[(b * NMX + i) * 2 + 1];
    const int w  = max(e - s, 0);
    const int valid = (i < n) ? 1 : 0;
    const int wv = valid ? w : 0;

    sh[i] = wv;
    __syncthreads();
    #pragma unroll
    for (int off = 1; off < NMX; off <<= 1) {
        int v = (i >= off) ? sh[i - off] : 0;
        __syncthreads();
        sh[i] += v;
        __syncthreads();
    }
    const int csum = sh[i];
    const int sn = csum - wv + i;         // compressed start
    const int en = csum + i;              // compressed end

    g_start[b][i] = valid ? sn : 0x3FFFFFFF;   // sentinel keeps array sorted
    g_end[b][i]   = en;
    g_src0[b][i]  = s;
    if (i == 0) g_n[b] = n;

    if (write_xi) {
        out_xi[(b * NMX + i) * 2 + 0] = valid ? (float)sn : 0.0f;
        out_xi[(b * NMX + i) * 2 + 1] = valid ? (float)en : 0.0f;
    }
}

// ---------------------------------------------------------------------------
// Kernel 2: the pack/gather. grid = (W/256, B, 4), block = 256.
// One thread per output column j; binary search over <=64 compressed starts
// in shared memory; then a 32-row loop (H split 4 ways over grid.z).
// Gather loads and stores are both coalesced along j.
// ---------------------------------------------------------------------------
__global__ void __launch_bounds__(256) pack_kernel(const float* __restrict__ x,
                                                   const float* __restrict__ sep_param,
                                                   float* __restrict__ out) {
    const int b = blockIdx.y;
    __shared__ int s_start[NMX];
    __shared__ int s_end[NMX];
    __shared__ int s_src[NMX];
    __shared__ int s_n;
    __shared__ float s_sep;

    const int t = threadIdx.x;
    if (t < NMX) {
        s_start[t] = g_start[b][t];
        s_end[t]   = g_end[b][t];
        s_src[t]   = g_src0[b][t];
    }
    if (t == 0) { s_n = g_n[b]; s_sep = sep_param[0]; }
    __syncthreads();

    const int j  = blockIdx.x * 256 + t;
    const int nc = s_n;

    // upper_bound(start, j) - 1  (searchsorted side='right' - 1)
    int lo = 0, hi = nc;
    while (lo < hi) {
        int mid = (lo + hi) >> 1;
        if (s_start[mid] <= j) lo = mid + 1; else hi = mid;
    }
    const int seg = lo - 1;

    bool  gather = false;
    int   src    = 0;
    float fill   = 0.0f;
    if (seg >= 0) {
        const int s = s_start[seg];
        const int e = s_end[seg];
        if (j < e) {
            gather = true;
            src = min(max(s_src[seg] + (j - s), 0), WW - 1);
        } else if (j == e && seg < nc - 1) {
            fill = s_sep;
        }
    }

    const int h0 = blockIdx.z * (HH / 4);
    const float* __restrict__ xb = x   + (size_t)b * HH * WW;
    float* __restrict__       ob = out + (size_t)b * HH * WW;

    #pragma unroll 8
    for (int hh = 0; hh < HH / 4; hh++) {
        const size_t row = (size_t)(h0 + hh) * WW;
        float v = gather ? __ldg(xb + row + src) : fill;
        ob[row + j] = v;
    }
}

// ---------------------------------------------------------------------------
extern "C" void kernel_launch(void* const* d_in, const int* in_sizes, int n_in,
                              void* d_out, int out_size) {
    const float* x   = (const float*)d_in[0];
    const int*   xi  = (const int*)  d_in[1];
    const int*   N   = (const int*)  d_in[2];
    const float* sep = (const float*)d_in[3];
    float*       out = (float*)d_out;

    const long long XN = (long long)BB * HH * WW;   // 16,777,216
    const int write_xi = ((long long)out_size > XN) ? 1 : 0;

    meta_kernel<<<BB, NMX>>>(xi, N, out + XN, write_xi);

    dim3 grid(WW / 256, BB, 4);
    pack_kernel<<<grid, 256>>>(x, sep, out);
}